// round 1
// baseline (speedup 1.0000x reference)
#include <cuda_runtime.h>

#define HIDDEN 128
#define NCOEF  8
#define KDIM   1152          // 128 (silu) + 128*8 (spline bases)
#define NPROTO 256
#define GRIDN  12
#define NMAX   131072
#define MT     32            // rows per block in layer GEMM
#define KC     32            // K chunk
#define RPB    64            // rows per block in cluster kernel

// ---------------- device scratch (no runtime allocation allowed) ----------------
__device__ float g_W1[KDIM * HIDDEN];
__device__ float g_W2[KDIM * HIDDEN];
__device__ float g_h[(size_t)NMAX * HIDDEN];      // layer-1 output
__device__ float g_pn[NPROTO * HIDDEN];           // normalized prototypes
__device__ float g_gridv[GRIDN];
__device__ float g_rd1[48];                       // 1/(G[j+p]-G[j]),   idx (p-1)*16+j
__device__ float g_rd2[48];                       // 1/(G[j+p+1]-G[j+1])

// ---------------- prep kernels ----------------
// Combined weight: k=i          -> base_w[o][i]
//                  k=128+c*128+i -> spline_w[o][i][c] * scaler[o][i]
// Layout W[k][o] (o contiguous) to match the layer kernel's A layout.
__global__ void prep_weights(const float* __restrict__ base_w,
                             const float* __restrict__ spline_w,
                             const float* __restrict__ scaler,
                             float* __restrict__ W) {
    int idx = blockIdx.x * blockDim.x + threadIdx.x;
    if (idx >= HIDDEN * HIDDEN) return;
    int o = idx / HIDDEN, i = idx % HIDDEN;
    W[(size_t)i * HIDDEN + o] = base_w[(size_t)o * HIDDEN + i];
    float sc = scaler[(size_t)o * HIDDEN + i];
#pragma unroll
    for (int c = 0; c < NCOEF; c++)
        W[(size_t)(HIDDEN + c * HIDDEN + i) * HIDDEN + o] =
            spline_w[((size_t)o * HIDDEN + i) * NCOEF + c] * sc;
}

__global__ void prep_grid(const float* __restrict__ grid) {
    if (threadIdx.x == 0) {
        for (int j = 0; j < GRIDN; j++) g_gridv[j] = grid[j];   // all rows identical
        for (int p = 1; p <= 3; p++)
            for (int j = 0; j + p + 1 < GRIDN; j++) {
                g_rd1[(p - 1) * 16 + j] = 1.0f / (grid[j + p] - grid[j]);
                g_rd2[(p - 1) * 16 + j] = 1.0f / (grid[j + p + 1] - grid[j + 1]);
            }
    }
}

__global__ void prep_protos(const float* __restrict__ protos) {
    int k = threadIdx.x;
    if (k >= NPROTO) return;
    float ss = 0.f;
    for (int i = 0; i < HIDDEN; i++) {
        float v = protos[(size_t)k * HIDDEN + i];
        ss += v * v;
    }
    float nrm = fmaxf(sqrtf(ss), 1e-8f);
    float inv = 1.0f / nrm;
    for (int i = 0; i < HIDDEN; i++)
        g_pn[(size_t)k * HIDDEN + i] = protos[(size_t)k * HIDDEN + i] * inv;
}

// ---------------- fused KAN layer: expand(silu + bsplines) then GEMM ----------------
__global__ void __launch_bounds__(256, 1)
kan_layer_kernel(const float* __restrict__ in, const float* __restrict__ W,
                 float* __restrict__ out) {
    extern __shared__ float sm[];
    float* sA = sm;                    // [MT][KDIM]  = 147456 B
    float* sW = sm + MT * KDIM;        // [KC][HIDDEN]= 16384 B
    __shared__ float sG[GRIDN];
    __shared__ float sR1[48], sR2[48];

    int tid = threadIdx.x;
    if (tid < GRIDN) sG[tid] = g_gridv[tid];
    if (tid < 48) { sR1[tid] = g_rd1[tid]; sR2[tid] = g_rd2[tid]; }
    __syncthreads();

    int m0 = blockIdx.x * MT;

    // ---- expansion: A[r] = [silu(x), bases (c-major)] ----
    for (int e = tid; e < MT * HIDDEN; e += 256) {
        int r = e >> 7, i = e & 127;
        float xv = in[(size_t)(m0 + r) * HIDDEN + i];
        float s = xv / (1.0f + __expf(-xv));
        sA[r * KDIM + i] = s;
        float b[11];
#pragma unroll
        for (int j = 0; j < 11; j++)
            b[j] = (xv >= sG[j] && xv < sG[j + 1]) ? 1.0f : 0.0f;
#pragma unroll
        for (int p = 1; p <= 3; p++) {
#pragma unroll
            for (int j = 0; j <= 10 - p; j++) {
                b[j] = (xv - sG[j]) * sR1[(p - 1) * 16 + j] * b[j]
                     + (sG[j + p + 1] - xv) * sR2[(p - 1) * 16 + j] * b[j + 1];
            }
        }
#pragma unroll
        for (int c = 0; c < NCOEF; c++)
            sA[r * KDIM + HIDDEN + c * HIDDEN + i] = b[c];   // i-contiguous: conflict-free STS
    }

    // ---- GEMM: out[32x128] = A[32x1152] @ W[1152x128] ----
    float acc[4][4];
#pragma unroll
    for (int a = 0; a < 4; a++)
#pragma unroll
        for (int c = 0; c < 4; c++) acc[a][c] = 0.f;

    int tr = tid >> 5;   // 0..7 -> rows tr*4..tr*4+3
    int tc = tid & 31;   // 0..31 -> cols tc*4..tc*4+3

    for (int k0 = 0; k0 < KDIM; k0 += KC) {
        __syncthreads();
        const float4* gw = (const float4*)(W + (size_t)k0 * HIDDEN);
#pragma unroll
        for (int l = 0; l < (KC * HIDDEN / 4) / 256; l++)
            ((float4*)sW)[tid + l * 256] = gw[tid + l * 256];
        __syncthreads();
#pragma unroll
        for (int kk = 0; kk < KC; kk++) {
            float a0 = sA[(tr * 4 + 0) * KDIM + k0 + kk];
            float a1 = sA[(tr * 4 + 1) * KDIM + k0 + kk];
            float a2 = sA[(tr * 4 + 2) * KDIM + k0 + kk];
            float a3 = sA[(tr * 4 + 3) * KDIM + k0 + kk];
            float4 w = ((float4*)sW)[kk * 32 + tc];
            acc[0][0] += a0 * w.x; acc[0][1] += a0 * w.y; acc[0][2] += a0 * w.z; acc[0][3] += a0 * w.w;
            acc[1][0] += a1 * w.x; acc[1][1] += a1 * w.y; acc[1][2] += a1 * w.z; acc[1][3] += a1 * w.w;
            acc[2][0] += a2 * w.x; acc[2][1] += a2 * w.y; acc[2][2] += a2 * w.z; acc[2][3] += a2 * w.w;
            acc[3][0] += a3 * w.x; acc[3][1] += a3 * w.y; acc[3][2] += a3 * w.z; acc[3][3] += a3 * w.w;
        }
    }

#pragma unroll
    for (int ri = 0; ri < 4; ri++) {
        float4 v = make_float4(acc[ri][0], acc[ri][1], acc[ri][2], acc[ri][3]);
        ((float4*)(out + (size_t)(m0 + tr * 4 + ri) * HIDDEN))[tc] = v;
    }
}

// ---------------- cosine argmax (norm of emb is a positive scalar -> argmax of raw dots vs normalized protos) ----------------
__global__ void __launch_bounds__(256, 1)
cluster_kernel(const float* __restrict__ emb, float* __restrict__ assignOut) {
    extern __shared__ float sm[];
    float* sPn  = sm;                      // [256][129] padded
    float* sRow = sm + NPROTO * 129;       // [4][128]
    __shared__ float sPv[8][4];
    __shared__ int   sPi[8][4];

    int tid = threadIdx.x;
    for (int l = tid; l < NPROTO * HIDDEN; l += 256) {
        int k = l >> 7, i = l & 127;
        sPn[k * 129 + i] = g_pn[l];
    }
    __syncthreads();

    int base = blockIdx.x * RPB;
    for (int r0 = 0; r0 < RPB; r0 += 4) {
        for (int l = tid; l < 4 * HIDDEN; l += 256)
            sRow[l] = emb[(size_t)(base + r0) * HIDDEN + l];
        __syncthreads();

        float d0 = 0.f, d1 = 0.f, d2 = 0.f, d3 = 0.f;
        const float* pk = sPn + tid * 129;
#pragma unroll 8
        for (int i = 0; i < HIDDEN; i++) {
            float w = pk[i];
            d0 += sRow[i] * w;
            d1 += sRow[128 + i] * w;
            d2 += sRow[256 + i] * w;
            d3 += sRow[384 + i] * w;
        }
        float dv[4] = {d0, d1, d2, d3};
#pragma unroll
        for (int j = 0; j < 4; j++) {
            float v = dv[j]; int bi = tid;
#pragma unroll
            for (int off = 16; off; off >>= 1) {
                float ov = __shfl_down_sync(0xffffffffu, v, off);
                int   oi = __shfl_down_sync(0xffffffffu, bi, off);
                if (ov > v || (ov == v && oi < bi)) { v = ov; bi = oi; }
            }
            if ((tid & 31) == 0) { sPv[tid >> 5][j] = v; sPi[tid >> 5][j] = bi; }
        }
        __syncthreads();
        if (tid < 4) {
            float v = sPv[0][tid]; int bi = sPi[0][tid];
#pragma unroll
            for (int w = 1; w < 8; w++) {
                float ov = sPv[w][tid]; int oi = sPi[w][tid];
                if (ov > v || (ov == v && oi < bi)) { v = ov; bi = oi; }
            }
            assignOut[base + r0 + tid] = (float)bi;
        }
        __syncthreads();
    }
}

// ---------------- launch ----------------
extern "C" void kernel_launch(void* const* d_in, const int* in_sizes, int n_in,
                              void* d_out, int out_size) {
    const float* x         = (const float*)d_in[0];
    const float* protos    = (const float*)d_in[1];
    const float* grid      = (const float*)d_in[2];
    const float* base_w1   = (const float*)d_in[3];
    const float* spline_w1 = (const float*)d_in[4];
    const float* scaler1   = (const float*)d_in[5];
    const float* base_w2   = (const float*)d_in[6];
    const float* spline_w2 = (const float*)d_in[7];
    const float* scaler2   = (const float*)d_in[8];

    int n = in_sizes[0] / HIDDEN;

    float *W1, *W2, *h;
    cudaGetSymbolAddress((void**)&W1, g_W1);
    cudaGetSymbolAddress((void**)&W2, g_W2);
    cudaGetSymbolAddress((void**)&h,  g_h);

    prep_weights<<<(HIDDEN * HIDDEN + 255) / 256, 256>>>(base_w1, spline_w1, scaler1, W1);
    prep_weights<<<(HIDDEN * HIDDEN + 255) / 256, 256>>>(base_w2, spline_w2, scaler2, W2);
    prep_grid<<<1, 32>>>(grid);
    prep_protos<<<1, NPROTO>>>(protos);

    size_t smemL = (size_t)(MT * KDIM + KC * HIDDEN) * sizeof(float);  // 163840 B
    cudaFuncSetAttribute(kan_layer_kernel, cudaFuncAttributeMaxDynamicSharedMemorySize, (int)smemL);

    float* emb = (float*)d_out;
    kan_layer_kernel<<<n / MT, 256, smemL>>>(x, W1, h);
    kan_layer_kernel<<<n / MT, 256, smemL>>>(h, W2, emb);

    if (out_size >= n * HIDDEN + n) {
        size_t smemC = (size_t)(NPROTO * 129 + 4 * HIDDEN) * sizeof(float);  // ~134 KB
        cudaFuncSetAttribute(cluster_kernel, cudaFuncAttributeMaxDynamicSharedMemorySize, (int)smemC);
        cluster_kernel<<<n / RPB, 256, smemC>>>(emb, emb + (size_t)n * HIDDEN);
    }
}